// round 13
// baseline (speedup 1.0000x reference)
#include <cuda_runtime.h>
#include <cuda_fp16.h>
#include <cstdint>
#include <cstddef>

// y = x @ (W + 2*A@B)^T + b ; x:[8192,4096] W:[4096,4096] r=16 (fp32 in/out)
// Single-pass fp16 mma.sync GEMM (X, Weff pre-rounded fp16; rel_err 2.9e-4).
// GEMM pinned at the sm_103 legacy-HMMA floor (~1 HMMA/16cyc/SMSP ~= 900 us).
// Prep (X->fp16 convert + LoRA fold into W) merged into ONE kernel with ILP=2.

#define M_TOT 8192
#define N_TOT 4096
#define K_TOT 4096
#define LORA_R 16

__device__ __align__(128) __half g_Xh[(size_t)M_TOT * K_TOT];  // 64 MB
__device__ __align__(128) __half g_Wh[(size_t)N_TOT * K_TOT];  // 32 MB

// ---------------------------------------------------------------------------
__device__ __forceinline__ uint32_t smem_u32(const void* p) {
    uint32_t a;
    asm("{ .reg .u64 t; cvta.to.shared.u64 t, %1; cvt.u32.u64 %0, t; }"
        : "=r"(a) : "l"(p));
    return a;
}
__device__ __forceinline__ void cp_async16(uint32_t dst, const void* src) {
    asm volatile("cp.async.cg.shared.global [%0], [%1], 16;"
                 :: "r"(dst), "l"(src) : "memory");
}
__device__ __forceinline__ void ldsm_x4(uint32_t (&r)[4], uint32_t addr) {
    asm volatile("ldmatrix.sync.aligned.m8n8.x4.shared.b16 {%0,%1,%2,%3}, [%4];"
                 : "=r"(r[0]), "=r"(r[1]), "=r"(r[2]), "=r"(r[3]) : "r"(addr));
}
__device__ __forceinline__ void mma16816(float (&d)[4], const uint32_t (&a)[4],
                                         uint32_t b0, uint32_t b1) {
    asm volatile(
        "mma.sync.aligned.m16n8k16.row.col.f32.f16.f16.f32 "
        "{%0,%1,%2,%3}, {%4,%5,%6,%7}, {%8,%9}, {%0,%1,%2,%3};"
        : "+f"(d[0]), "+f"(d[1]), "+f"(d[2]), "+f"(d[3])
        : "r"(a[0]), "r"(a[1]), "r"(a[2]), "r"(a[3]), "r"(b0), "r"(b1));
}

// ---------------------------------------------------------------------------
// Merged prep kernel.
// Blocks [0, XBLK): convert X fp32 -> fp16, 2 float4 per thread (ILP=2).
// Blocks [XBLK, XBLK+WBLK): fold LoRA into W row, round to fp16, ILP=2.
// ---------------------------------------------------------------------------
#define XBLK ((unsigned)((size_t)M_TOT * K_TOT / 4 / 512))  // 16384
#define WBLK ((unsigned)(N_TOT * 2))                        // 8192 (2 blocks/row)

__global__ __launch_bounds__(256)
void prep_kernel(const float* __restrict__ X,
                 const float* __restrict__ W,
                 const float* __restrict__ A,    // [N, R]
                 const float* __restrict__ B) {  // [R, K]
    if (blockIdx.x < XBLK) {
        // --- X conversion: 2 independent float4 chains per thread ---
        const size_t base = (size_t)blockIdx.x * 512 + threadIdx.x;
        const float4 v0 = reinterpret_cast<const float4*>(X)[base];
        const float4 v1 = reinterpret_cast<const float4*>(X)[base + 256];
        __half2* p0 = reinterpret_cast<__half2*>(g_Xh) + 2 * base;
        __half2* p1 = reinterpret_cast<__half2*>(g_Xh) + 2 * (base + 256);
        p0[0] = __floats2half2_rn(v0.x, v0.y);
        p0[1] = __floats2half2_rn(v0.z, v0.w);
        p1[0] = __floats2half2_rn(v1.x, v1.y);
        p1[1] = __floats2half2_rn(v1.z, v1.w);
    } else {
        // --- W fold: block handles half a row (512 float4), 2 per thread ---
        __shared__ float a_sh[LORA_R];
        const unsigned b = blockIdx.x - XBLK;
        const int o = (int)(b >> 1);
        const int half = (int)(b & 1);
        if (threadIdx.x < LORA_R)
            a_sh[threadIdx.x] = A[(size_t)o * LORA_R + threadIdx.x];
        __syncthreads();

        const int i0 = half * 512 + (int)threadIdx.x;   // float4 index in row
        const int i1 = i0 + 256;
        const float4* Wrow = reinterpret_cast<const float4*>(W + (size_t)o * K_TOT);
        float4 w0 = Wrow[i0];
        float4 w1 = Wrow[i1];
        float4 a0 = make_float4(0.f, 0.f, 0.f, 0.f);
        float4 a1 = make_float4(0.f, 0.f, 0.f, 0.f);
#pragma unroll
        for (int r = 0; r < LORA_R; r++) {
            const float4* Brow = reinterpret_cast<const float4*>(B + (size_t)r * K_TOT);
            const float4 b0 = Brow[i0];
            const float4 b1 = Brow[i1];
            const float a = a_sh[r];
            a0.x += a * b0.x; a0.y += a * b0.y; a0.z += a * b0.z; a0.w += a * b0.w;
            a1.x += a * b1.x; a1.y += a * b1.y; a1.z += a * b1.z; a1.w += a * b1.w;
        }
        __half2* p = reinterpret_cast<__half2*>(g_Wh + (size_t)o * K_TOT);
        p[2 * i0 + 0] = __floats2half2_rn(w0.x + 2.f * a0.x, w0.y + 2.f * a0.y);
        p[2 * i0 + 1] = __floats2half2_rn(w0.z + 2.f * a0.z, w0.w + 2.f * a0.w);
        p[2 * i1 + 0] = __floats2half2_rn(w1.x + 2.f * a1.x, w1.y + 2.f * a1.y);
        p[2 * i1 + 1] = __floats2half2_rn(w1.z + 2.f * a1.z, w1.w + 2.f * a1.w);
    }
}

// ---------------------------------------------------------------------------
// GEMM: 128x128 CTA tile, BK=32, 8 warps (2m x 4n), warp tile 64x32,
// 4 smem stages, simple inline kc loop (R11 config — at the HMMA floor).
// SMEM rows padded to 80B: ldmatrix conflict-free (row stride 20 banks).
// ---------------------------------------------------------------------------
#define BM 128
#define BN 128
#define BK 32
#define STAGES 4
#define ROW_B 80
#define TILE_B (128 * ROW_B)           // 10240 per operand
#define STAGE_B (2 * TILE_B)           // 20480
#define SMEM_TOTAL (STAGES * STAGE_B)  // 81920
#define ITERS (K_TOT / BK)             // 128

__global__ __launch_bounds__(256, 2)
void gemm_mma_kernel(const float* __restrict__ bias, float* __restrict__ Y) {
    extern __shared__ __align__(128) char smem[];
    const uint32_t sb = smem_u32(smem);
    const int tid = threadIdx.x;
    const int lid = tid & 31;
    const int wid = tid >> 5;
    const int wm = (wid & 1) * 64;
    const int wn = (wid >> 1) * 32;

    const size_t bm = (size_t)blockIdx.y * BM;
    const size_t bn = (size_t)blockIdx.x * BN;

    uint32_t soff[2], gA[2], gB[2];
#pragma unroll
    for (int t = 0; t < 2; t++) {
        const int f = tid + t * 256;
        const int row = f >> 2;
        const int c = f & 3;
        soff[t] = (uint32_t)(row * ROW_B + c * 16);
        gA[t] = (uint32_t)(((bm + row) * K_TOT + c * 8) * 2);
        gB[t] = (uint32_t)(((bn + row) * K_TOT + c * 8) * 2);
    }
    const char* Xb = reinterpret_cast<const char*>(g_Xh);
    const char* Wb = reinterpret_cast<const char*>(g_Wh);

    auto load_stage = [&](int s, int j) {
        if (j < ITERS) {
            const uint32_t k0 = (uint32_t)j * (BK * 2);
            const uint32_t aB = sb + (uint32_t)s * STAGE_B;
            const uint32_t bB = aB + TILE_B;
#pragma unroll
            for (int t = 0; t < 2; t++) {
                cp_async16(aB + soff[t], Xb + k0 + gA[t]);
                cp_async16(bB + soff[t], Wb + k0 + gB[t]);
            }
        }
        asm volatile("cp.async.commit_group;" ::: "memory");
    };

    float acc[4][4][4];
#pragma unroll
    for (int i = 0; i < 4; i++)
#pragma unroll
        for (int j = 0; j < 4; j++)
#pragma unroll
            for (int q = 0; q < 4; q++) acc[i][j][q] = 0.f;

    const int lrow = lid & 15;
    const int lkh = lid >> 4;
    const int kcflip = wid & 1;

#pragma unroll
    for (int s = 0; s < STAGES - 1; s++) load_stage(s, s);

    for (int i = 0; i < ITERS; i++) {
        asm volatile("cp.async.wait_group %0;" :: "n"(STAGES - 2) : "memory");
        __syncthreads();

        load_stage((i + STAGES - 1) & (STAGES - 1), i + STAGES - 1);

        const int s = i & (STAGES - 1);
        const uint32_t aB = sb + (uint32_t)s * STAGE_B;
        const uint32_t bB = aB + TILE_B;

#pragma unroll
        for (int kx = 0; kx < 2; kx++) {
            const int kc = kx ^ kcflip;
            const uint32_t koff = (uint32_t)((kc * 16 + lkh * 8) * 2);
            uint32_t a[4][4], br[2][4];
#pragma unroll
            for (int mg = 0; mg < 4; mg++)
                ldsm_x4(a[mg], aB + (uint32_t)((wm + mg * 16 + lrow) * ROW_B) + koff);
#pragma unroll
            for (int np = 0; np < 2; np++)
                ldsm_x4(br[np], bB + (uint32_t)((wn + np * 16 + lrow) * ROW_B) + koff);
#pragma unroll
            for (int mg = 0; mg < 4; mg++)
#pragma unroll
                for (int ng = 0; ng < 4; ng++)
                    mma16816(acc[mg][ng], a[mg],
                             br[ng >> 1][ng & 1], br[ng >> 1][(ng & 1) + 2]);
        }
    }

#pragma unroll
    for (int ng = 0; ng < 4; ng++) {
        const size_t c = bn + wn + ng * 8 + (lid & 3) * 2;
        const float2 bv = *reinterpret_cast<const float2*>(bias + c);
#pragma unroll
        for (int mg = 0; mg < 4; mg++) {
            const size_t r = bm + wm + mg * 16 + (lid >> 2);
            float2 o0, o1;
            o0.x = acc[mg][ng][0] + bv.x;
            o0.y = acc[mg][ng][1] + bv.y;
            o1.x = acc[mg][ng][2] + bv.x;
            o1.y = acc[mg][ng][3] + bv.y;
            *reinterpret_cast<float2*>(Y + r * N_TOT + c) = o0;
            *reinterpret_cast<float2*>(Y + (r + 8) * N_TOT + c) = o1;
        }
    }
}

// ---------------------------------------------------------------------------
extern "C" void kernel_launch(void* const* d_in, const int* in_sizes, int n_in,
                              void* d_out, int out_size) {
    const float* x  = (const float*)d_in[0];
    const float* W  = (const float*)d_in[1];
    const float* b  = (const float*)d_in[2];
    const float* lA = (const float*)d_in[3];
    const float* lB = (const float*)d_in[4];
    float* y = (float*)d_out;

    prep_kernel<<<XBLK + WBLK, 256>>>(x, W, lA, lB);

    cudaFuncSetAttribute(gemm_mma_kernel,
                         cudaFuncAttributeMaxDynamicSharedMemorySize, SMEM_TOTAL);
    dim3 grid(N_TOT / BN, M_TOT / BM);  // (32, 64) — n-fastest raster
    gemm_mma_kernel<<<grid, 256, SMEM_TOTAL>>>(b, y);
}

// round 14
// speedup vs baseline: 1.5427x; 1.5427x over previous
#include <cuda_runtime.h>
#include <cuda_fp16.h>
#include <cstdint>
#include <cstddef>

// y = x @ (W + 2*A@B)^T + b ; x:[8192,4096] W:[4096,4096] r=16 (fp32 in/out)
// Single-pass fp16 mma.sync GEMM (X, Weff pre-rounded fp16; rel_err 2.9e-4).
// R11 configuration restored verbatim (948 us): separate prep kernels, GEMM
// = 256 threads, 8 warps (2m x 4n), warp tile 64x32, simple inline kc loop,
// 4-stage cp.async. Only delta vs R11: conv_x uses ILP=2.

#define M_TOT 8192
#define N_TOT 4096
#define K_TOT 4096
#define LORA_R 16

__device__ __align__(128) __half g_Xh[(size_t)M_TOT * K_TOT];  // 64 MB
__device__ __align__(128) __half g_Wh[(size_t)N_TOT * K_TOT];  // 32 MB

// ---------------------------------------------------------------------------
__device__ __forceinline__ uint32_t smem_u32(const void* p) {
    uint32_t a;
    asm("{ .reg .u64 t; cvta.to.shared.u64 t, %1; cvt.u32.u64 %0, t; }"
        : "=r"(a) : "l"(p));
    return a;
}
__device__ __forceinline__ void cp_async16(uint32_t dst, const void* src) {
    asm volatile("cp.async.cg.shared.global [%0], [%1], 16;"
                 :: "r"(dst), "l"(src) : "memory");
}
__device__ __forceinline__ void ldsm_x4(uint32_t (&r)[4], uint32_t addr) {
    asm volatile("ldmatrix.sync.aligned.m8n8.x4.shared.b16 {%0,%1,%2,%3}, [%4];"
                 : "=r"(r[0]), "=r"(r[1]), "=r"(r[2]), "=r"(r[3]) : "r"(addr));
}
__device__ __forceinline__ void mma16816(float (&d)[4], const uint32_t (&a)[4],
                                         uint32_t b0, uint32_t b1) {
    asm volatile(
        "mma.sync.aligned.m16n8k16.row.col.f32.f16.f16.f32 "
        "{%0,%1,%2,%3}, {%4,%5,%6,%7}, {%8,%9}, {%0,%1,%2,%3};"
        : "+f"(d[0]), "+f"(d[1]), "+f"(d[2]), "+f"(d[3])
        : "r"(a[0]), "r"(a[1]), "r"(a[2]), "r"(a[3]), "r"(b0), "r"(b1));
}

// ---------------------------------------------------------------------------
// Prep kernels (separate launches — merging them regressed the GEMM in R13)
// ---------------------------------------------------------------------------
__global__ __launch_bounds__(256)
void conv_x_kernel(const float* __restrict__ X) {
    const size_t base = (size_t)blockIdx.x * 512 + threadIdx.x;  // float4 index
    const float4 v0 = reinterpret_cast<const float4*>(X)[base];
    const float4 v1 = reinterpret_cast<const float4*>(X)[base + 256];
    __half2* p0 = reinterpret_cast<__half2*>(g_Xh) + 2 * base;
    __half2* p1 = reinterpret_cast<__half2*>(g_Xh) + 2 * (base + 256);
    p0[0] = __floats2half2_rn(v0.x, v0.y);
    p0[1] = __floats2half2_rn(v0.z, v0.w);
    p1[0] = __floats2half2_rn(v1.x, v1.y);
    p1[1] = __floats2half2_rn(v1.z, v1.w);
}

__global__ __launch_bounds__(256)
void fold_w_kernel(const float* __restrict__ W,
                   const float* __restrict__ A,    // [N, R]
                   const float* __restrict__ B) {  // [R, K]
    __shared__ float a_sh[LORA_R];
    const int o = blockIdx.y;
    if (threadIdx.x < LORA_R)
        a_sh[threadIdx.x] = A[(size_t)o * LORA_R + threadIdx.x];
    __syncthreads();

    const int i4 = blockIdx.x * 256 + threadIdx.x;
    float4 w = reinterpret_cast<const float4*>(W + (size_t)o * K_TOT)[i4];
    float4 acc = make_float4(0.f, 0.f, 0.f, 0.f);
#pragma unroll
    for (int r = 0; r < LORA_R; r++) {
        const float4 bv = reinterpret_cast<const float4*>(B + (size_t)r * K_TOT)[i4];
        const float a = a_sh[r];
        acc.x += a * bv.x; acc.y += a * bv.y; acc.z += a * bv.z; acc.w += a * bv.w;
    }
    __half2* p = reinterpret_cast<__half2*>(g_Wh + (size_t)o * K_TOT) + 2 * i4;
    p[0] = __floats2half2_rn(w.x + 2.f * acc.x, w.y + 2.f * acc.y);
    p[1] = __floats2half2_rn(w.z + 2.f * acc.z, w.w + 2.f * acc.w);
}

// ---------------------------------------------------------------------------
// GEMM: 128x128 CTA tile, BK=32, 8 warps (2m x 4n), warp tile 64x32,
// 4 smem stages, simple inline kc loop (R11 config — at the HMMA floor).
// SMEM rows padded to 80B: ldmatrix conflict-free (row stride 20 banks).
// ---------------------------------------------------------------------------
#define BM 128
#define BN 128
#define BK 32
#define STAGES 4
#define ROW_B 80
#define TILE_B (128 * ROW_B)           // 10240 per operand
#define STAGE_B (2 * TILE_B)           // 20480
#define SMEM_TOTAL (STAGES * STAGE_B)  // 81920
#define ITERS (K_TOT / BK)             // 128

__global__ __launch_bounds__(256, 2)
void gemm_mma_kernel(const float* __restrict__ bias, float* __restrict__ Y) {
    extern __shared__ __align__(128) char smem[];
    const uint32_t sb = smem_u32(smem);
    const int tid = threadIdx.x;
    const int lid = tid & 31;
    const int wid = tid >> 5;
    const int wm = (wid & 1) * 64;     // warp M offset
    const int wn = (wid >> 1) * 32;    // warp N offset

    const size_t bm = (size_t)blockIdx.y * BM;
    const size_t bn = (size_t)blockIdx.x * BN;

    // Cooperative loads: per operand 512 x 16B chunks, 2 per thread.
    uint32_t soff[2], gA[2], gB[2];    // global offsets in bytes (fit u32)
#pragma unroll
    for (int t = 0; t < 2; t++) {
        const int f = tid + t * 256;
        const int row = f >> 2;
        const int c = f & 3;
        soff[t] = (uint32_t)(row * ROW_B + c * 16);
        gA[t] = (uint32_t)(((bm + row) * K_TOT + c * 8) * 2);
        gB[t] = (uint32_t)(((bn + row) * K_TOT + c * 8) * 2);
    }
    const char* Xb = reinterpret_cast<const char*>(g_Xh);
    const char* Wb = reinterpret_cast<const char*>(g_Wh);

    auto load_stage = [&](int s, int j) {
        if (j < ITERS) {
            const uint32_t k0 = (uint32_t)j * (BK * 2);
            const uint32_t aB = sb + (uint32_t)s * STAGE_B;
            const uint32_t bB = aB + TILE_B;
#pragma unroll
            for (int t = 0; t < 2; t++) {
                cp_async16(aB + soff[t], Xb + k0 + gA[t]);
                cp_async16(bB + soff[t], Wb + k0 + gB[t]);
            }
        }
        asm volatile("cp.async.commit_group;" ::: "memory");
    };

    float acc[4][4][4];
#pragma unroll
    for (int i = 0; i < 4; i++)
#pragma unroll
        for (int j = 0; j < 4; j++)
#pragma unroll
            for (int q = 0; q < 4; q++) acc[i][j][q] = 0.f;

    const int lrow = lid & 15;
    const int lkh = lid >> 4;
    const int kcflip = wid & 1;        // odd warps run kc in reverse order

#pragma unroll
    for (int s = 0; s < STAGES - 1; s++) load_stage(s, s);

    for (int i = 0; i < ITERS; i++) {
        asm volatile("cp.async.wait_group %0;" :: "n"(STAGES - 2) : "memory");
        __syncthreads();

        load_stage((i + STAGES - 1) & (STAGES - 1), i + STAGES - 1);

        const int s = i & (STAGES - 1);
        const uint32_t aB = sb + (uint32_t)s * STAGE_B;
        const uint32_t bB = aB + TILE_B;

#pragma unroll
        for (int kx = 0; kx < 2; kx++) {
            const int kc = kx ^ kcflip;
            const uint32_t koff = (uint32_t)((kc * 16 + lkh * 8) * 2);
            uint32_t a[4][4], br[2][4];
#pragma unroll
            for (int mg = 0; mg < 4; mg++)
                ldsm_x4(a[mg], aB + (uint32_t)((wm + mg * 16 + lrow) * ROW_B) + koff);
#pragma unroll
            for (int np = 0; np < 2; np++)
                ldsm_x4(br[np], bB + (uint32_t)((wn + np * 16 + lrow) * ROW_B) + koff);
#pragma unroll
            for (int mg = 0; mg < 4; mg++)
#pragma unroll
                for (int ng = 0; ng < 4; ng++)
                    mma16816(acc[mg][ng], a[mg],
                             br[ng >> 1][ng & 1], br[ng >> 1][(ng & 1) + 2]);
        }
    }

    // Epilogue: add bias, float2 stores.
#pragma unroll
    for (int ng = 0; ng < 4; ng++) {
        const size_t c = bn + wn + ng * 8 + (lid & 3) * 2;
        const float2 bv = *reinterpret_cast<const float2*>(bias + c);
#pragma unroll
        for (int mg = 0; mg < 4; mg++) {
            const size_t r = bm + wm + mg * 16 + (lid >> 2);
            float2 o0, o1;
            o0.x = acc[mg][ng][0] + bv.x;
            o0.y = acc[mg][ng][1] + bv.y;
            o1.x = acc[mg][ng][2] + bv.x;
            o1.y = acc[mg][ng][3] + bv.y;
            *reinterpret_cast<float2*>(Y + r * N_TOT + c) = o0;
            *reinterpret_cast<float2*>(Y + (r + 8) * N_TOT + c) = o1;
        }
    }
}

// ---------------------------------------------------------------------------
extern "C" void kernel_launch(void* const* d_in, const int* in_sizes, int n_in,
                              void* d_out, int out_size) {
    const float* x  = (const float*)d_in[0];
    const float* W  = (const float*)d_in[1];
    const float* b  = (const float*)d_in[2];
    const float* lA = (const float*)d_in[3];
    const float* lB = (const float*)d_in[4];
    float* y = (float*)d_out;

    conv_x_kernel<<<(unsigned)((size_t)M_TOT * K_TOT / 4 / 512), 256>>>(x);
    fold_w_kernel<<<dim3(K_TOT / 1024, N_TOT), 256>>>(W, lA, lB);

    cudaFuncSetAttribute(gemm_mma_kernel,
                         cudaFuncAttributeMaxDynamicSharedMemorySize, SMEM_TOTAL);
    dim3 grid(N_TOT / BN, M_TOT / BM);  // (32, 64) — n-fastest raster
    gemm_mma_kernel<<<grid, 256, SMEM_TOTAL>>>(b, y);
}